// round 5
// baseline (speedup 1.0000x reference)
#include <cuda_runtime.h>
#include <math.h>

#define N_NODES 8192
#define NEDGE   131072
#define BGR     32
#define NELEM   5
#define NCOMP   160
#define NPAIR   800          // 32 graphs * 5 * 5
#define HH      128
#define GG      50
#define LL      6
#define MT      512          // distance-table samples
#define NBCOL   (LL*HH)      // 768
#define EWMAX   20.0f

static __device__ float g_R[NPAIR*MT];        // pair x bin accumulation of C * hat-basis
static __device__ float g_csum[NPAIR];        // sum of C per pair
static __device__ int   g_counts[NCOMP];      // nodes per component
static __device__ float g_phi[MT*NBCOL];      // ssp(edge_attr@w1+b1) sampled on distance grid
static __device__ float g_tableW[MT*NBCOL];   // g_phi @ w2 (per layer)
static __device__ float g_S[NPAIR*NBCOL];     // R @ tableW
static __device__ float g_xout[LL*NCOMP*HH];  // per-layer additive update to types

__device__ __forceinline__ float sspf(float x) {
    // shifted softplus: log(1+e^x) - log 2, numerically stable
    return fmaxf(x, 0.0f) + log1pf(expf(-fabsf(x))) - 0.69314718055994531f;
}

// --------------------------------------------------------------------------
__global__ void k_zero() {
    int i = blockIdx.x * blockDim.x + threadIdx.x;
    int stride = gridDim.x * blockDim.x;
    for (int j = i; j < NPAIR*MT;    j += stride) g_R[j]    = 0.0f;
    for (int j = i; j < NPAIR*NBCOL; j += stride) g_S[j]    = 0.0f;
    for (int j = i; j < NPAIR;       j += stride) g_csum[j] = 0.0f;
    for (int j = i; j < NCOMP;       j += stride) g_counts[j] = 0;
}

// --------------------------------------------------------------------------
__global__ void k_counts(const int* __restrict__ comp_id) {
    int n = blockIdx.x * blockDim.x + threadIdx.x;
    if (n < N_NODES) atomicAdd(&g_counts[comp_id[n]], 1);
}

// --------------------------------------------------------------------------
// Per-edge: distance, cutoff weight C, pair id, 2-point hat-basis scatter into R.
__global__ void k_edges(const float* __restrict__ pos,
                        const int*   __restrict__ comp_id,
                        const int*   __restrict__ ei) {
    const float INV_DELTA = (float)(MT - 1) / EWMAX;
    int e = blockIdx.x * blockDim.x + threadIdx.x;
    if (e >= NEDGE) return;
    int s = ei[e];
    int d = ei[NEDGE + e];
    int cs = comp_id[s];
    int cd = comp_id[d];
    float dx = pos[3*s+0] - pos[3*d+0];
    float dy = pos[3*s+1] - pos[3*d+1];
    float dz = pos[3*s+2] - pos[3*d+2];
    float ew = sqrtf(dx*dx + dy*dy + dz*dz);
    float C  = 10.0f / (1e-10f + ew*ew) - 1.0f;
    int p = (cd / NELEM) * 25 + (cs % NELEM) * NELEM + (cd % NELEM);
    float tf = fminf(ew * INV_DELTA, (float)(MT - 1));
    int   i0 = min((int)tf, MT - 2);
    float fr = tf - (float)i0;
    atomicAdd(&g_R[p*MT + i0],     C * (1.0f - fr));
    atomicAdd(&g_R[p*MT + i0 + 1], C * fr);
    atomicAdd(&g_csum[p], C);
}

// --------------------------------------------------------------------------
// Build phi[m][l*128+f] = ssp( sum_g exp(coeff*(t_m - o_g)^2) * w1[l][g][f] + b1[l][f] )
__global__ void k_phi(const float* __restrict__ w1, const float* __restrict__ b1) {
    const float DELTA = EWMAX / (float)(MT - 1);
    const float OFFD  = 10.0f / 49.0f;
    const float COEFF = -0.5f / (OFFD * OFFD);
    __shared__ float a[8][GG];
    int m0 = blockIdx.x * 8;
    int tid = threadIdx.x;
    for (int idx = tid; idx < 8*GG; idx += 128) {
        int mm = idx / GG, g = idx % GG;
        float t  = (float)(m0 + mm) * DELTA;
        float dt = t - (float)g * OFFD;
        a[mm][g] = expf(COEFF * dt * dt);
    }
    __syncthreads();
    int f = tid;  // 0..127
    for (int l = 0; l < LL; l++) {
        float acc[8];
        float bb = b1[l*HH + f];
        #pragma unroll
        for (int mm = 0; mm < 8; mm++) acc[mm] = bb;
        for (int g = 0; g < GG; g++) {
            float w = w1[(l*GG + g)*HH + f];
            #pragma unroll
            for (int mm = 0; mm < 8; mm++) acc[mm] += a[mm][g] * w;
        }
        #pragma unroll
        for (int mm = 0; mm < 8; mm++)
            g_phi[(m0 + mm)*NBCOL + l*HH + f] = sspf(acc[mm]);
    }
}

// --------------------------------------------------------------------------
// tableW[m][l*128+f] = sum_k phi[m][l*128+k] * w2[l][k][f]  (fold mlp_w2 into table)
__global__ void k_tw2(const float* __restrict__ w2) {
    __shared__ float sp[16][HH];
    int m0 = blockIdx.x * 16;
    int l  = blockIdx.y;
    int f  = threadIdx.x;
    for (int mm = 0; mm < 16; mm++)
        sp[mm][f] = g_phi[(m0 + mm)*NBCOL + l*HH + f];
    __syncthreads();
    float acc[16];
    #pragma unroll
    for (int mm = 0; mm < 16; mm++) acc[mm] = 0.0f;
    for (int k = 0; k < HH; k++) {
        float w = w2[(l*HH + k)*HH + f];
        #pragma unroll
        for (int mm = 0; mm < 16; mm++) acc[mm] += sp[mm][k] * w;
    }
    #pragma unroll
    for (int mm = 0; mm < 16; mm++)
        g_tableW[(m0 + mm)*NBCOL + l*HH + f] = acc[mm];
}

// --------------------------------------------------------------------------
// S[800,768] = R[800,512] @ tableW[512,768], split-K=2 with atomic accumulate.
#define BM 64
#define BN 128
#define BK 32
__global__ void k_gemm() {
    __shared__ float Rs[BM][BK + 1];
    __shared__ float Ts[BK][BN];
    int tid  = threadIdx.x;            // 256
    int row0 = blockIdx.x * BM;
    int col0 = blockIdx.y * BN;
    int kb   = blockIdx.z * (MT / 2);
    int ty = tid >> 5, tx = tid & 31;
    int r0 = ty * 8,   c0 = tx * 4;
    float acc[8][4];
    #pragma unroll
    for (int i = 0; i < 8; i++)
        #pragma unroll
        for (int j = 0; j < 4; j++) acc[i][j] = 0.0f;

    for (int kk = 0; kk < MT/2; kk += BK) {
        int lr = tid >> 2;
        int lk = (tid & 3) * 8;
        int grow = row0 + lr;
        #pragma unroll
        for (int i = 0; i < 8; i++)
            Rs[lr][lk + i] = (grow < NPAIR) ? g_R[grow*MT + kb + kk + lk + i] : 0.0f;
        int tc  = (tid & 31) * 4;
        int tr0 = tid >> 5;
        #pragma unroll
        for (int j = 0; j < 4; j++) {
            int r = tr0 + j * 8;
            float4 v = *reinterpret_cast<const float4*>(
                &g_tableW[(kb + kk + r)*NBCOL + col0 + tc]);
            *reinterpret_cast<float4*>(&Ts[r][tc]) = v;
        }
        __syncthreads();
        #pragma unroll
        for (int k = 0; k < BK; k++) {
            float4 b = *reinterpret_cast<const float4*>(&Ts[k][c0]);
            #pragma unroll
            for (int i = 0; i < 8; i++) {
                float a = Rs[r0 + i][k];
                acc[i][0] += a * b.x;
                acc[i][1] += a * b.y;
                acc[i][2] += a * b.z;
                acc[i][3] += a * b.w;
            }
        }
        __syncthreads();
    }
    #pragma unroll
    for (int i = 0; i < 8; i++) {
        int gr = row0 + r0 + i;
        if (gr < NPAIR) {
            #pragma unroll
            for (int j = 0; j < 4; j++)
                atomicAdd(&g_S[gr*NBCOL + col0 + c0 + j], acc[i][j]);
        }
    }
}

// --------------------------------------------------------------------------
// Per (graph, layer): comp -> cf_lin2 -> ssp -> int_lin, write additive types update.
__global__ void k_comp(const int*   __restrict__ comps_z,
                       const float* __restrict__ emb,
                       const float* __restrict__ cf1,
                       const float* __restrict__ b2,
                       const float* __restrict__ cf2w,
                       const float* __restrict__ cf2b,
                       const float* __restrict__ ilw,
                       const float* __restrict__ ilb) {
    __shared__ float xh [NELEM][HH];
    __shared__ float buf[NELEM][HH];
    __shared__ float semb[HH];
    int g = blockIdx.x, l = blockIdx.y;
    int f = threadIdx.x;

    for (int s = 0; s < NELEM; s++) {
        int zz = comps_z[g*NELEM + s];
        semb[f] = emb[zz*HH + f];
        __syncthreads();
        float acc = 0.0f;
        for (int h = 0; h < HH; h++) acc += semb[h] * cf1[(l*HH + h)*HH + f];
        xh[s][f] = acc;
        __syncthreads();
    }

    float bb2 = b2[l*HH + f];
    for (int t = 0; t < NELEM; t++) {
        float acc = 0.0f;
        #pragma unroll
        for (int s = 0; s < NELEM; s++) {
            int p = g*25 + s*NELEM + t;
            float Sv = g_S[p*NBCOL + l*HH + f] + bb2 * g_csum[p];
            acc += xh[s][f] * Sv;
        }
        int c = g*NELEM + t;
        buf[t][f] = acc / (float)g_counts[c];
    }
    __syncthreads();

    for (int t = 0; t < NELEM; t++) {
        float acc = cf2b[l*HH + f];
        for (int h = 0; h < HH; h++) acc += buf[t][h] * cf2w[(l*HH + h)*HH + f];
        xh[t][f] = sspf(acc);   // reuse xh as ssp(x1)
    }
    __syncthreads();

    for (int t = 0; t < NELEM; t++) {
        float acc = ilb[l*HH + f];
        for (int h = 0; h < HH; h++) acc += xh[t][h] * ilw[(l*HH + h)*HH + f];
        g_xout[(l*NCOMP + g*NELEM + t)*HH + f] = acc;
    }
}

// --------------------------------------------------------------------------
// Readout per graph: types = emb + sum_l x_l ; out[g] = sum_c (ssp(types@w1+b1)@w2 + b2)
__global__ void k_readout(const int*   __restrict__ comps_z,
                          const float* __restrict__ emb,
                          const float* __restrict__ ow1,
                          const float* __restrict__ ob1,
                          const float* __restrict__ ow2,
                          const float* __restrict__ ob2,
                          float* __restrict__ out) {
    __shared__ float types[NELEM][HH];
    __shared__ float wsum[2];
    int g = blockIdx.x;
    int tid = threadIdx.x;  // 128

    for (int s = 0; s < NELEM; s++) {
        int c = g*NELEM + s;
        float v = emb[comps_z[c]*HH + tid];
        #pragma unroll
        for (int l = 0; l < LL; l++) v += g_xout[(l*NCOMP + c)*HH + tid];
        types[s][tid] = v;
    }
    __syncthreads();

    float pc = 0.0f;
    if (tid < 64) {
        for (int s = 0; s < NELEM; s++) {
            float u = ob1[tid];
            for (int h = 0; h < HH; h++) u += types[s][h] * ow1[h*64 + tid];
            pc += sspf(u) * ow2[tid];
        }
    }
    #pragma unroll
    for (int off = 16; off > 0; off >>= 1)
        pc += __shfl_down_sync(0xffffffff, pc, off);
    if ((tid & 31) == 0 && tid < 64) wsum[tid >> 5] = pc;
    __syncthreads();
    if (tid == 0) out[g] = wsum[0] + wsum[1] + 5.0f * ob2[0];
}

// --------------------------------------------------------------------------
extern "C" void kernel_launch(void* const* d_in, const int* in_sizes, int n_in,
                              void* d_out, int out_size) {
    const float* pos      = (const float*)d_in[0];
    const float* emb      = (const float*)d_in[1];
    const float* mlp_w1   = (const float*)d_in[2];
    const float* mlp_b1   = (const float*)d_in[3];
    const float* mlp_w2   = (const float*)d_in[4];
    const float* mlp_b2   = (const float*)d_in[5];
    const float* cf1w     = (const float*)d_in[6];
    const float* cf2w     = (const float*)d_in[7];
    const float* cf2b     = (const float*)d_in[8];
    const float* ilw      = (const float*)d_in[9];
    const float* ilb      = (const float*)d_in[10];
    const float* ow1      = (const float*)d_in[11];
    const float* ob1      = (const float*)d_in[12];
    const float* ow2      = (const float*)d_in[13];
    const float* ob2      = (const float*)d_in[14];
    // d_in[15] = z (unused: z[n] == comps_z[comp_id[n]] by construction)
    const int*   comp_id  = (const int*)d_in[16];
    const int*   ei       = (const int*)d_in[17];
    const int*   comps_z  = (const int*)d_in[18];
    float*       out      = (float*)d_out;

    k_zero  <<<256, 256>>>();
    k_counts<<<(N_NODES + 255)/256, 256>>>(comp_id);
    k_edges <<<(NEDGE + 255)/256, 256>>>(pos, comp_id, ei);
    k_phi   <<<MT/8, 128>>>(mlp_w1, mlp_b1);
    k_tw2   <<<dim3(MT/16, LL), 128>>>(mlp_w2);
    k_gemm  <<<dim3((NPAIR + BM - 1)/BM, NBCOL/BN, 2), 256>>>();
    k_comp  <<<dim3(BGR, LL), 128>>>(comps_z, emb, cf1w, mlp_b2, cf2w, cf2b, ilw, ilb);
    k_readout<<<BGR, 128>>>(comps_z, emb, ow1, ob1, ow2, ob2, out);
}

// round 12
// speedup vs baseline: 1.7747x; 1.7747x over previous
#include <cuda_runtime.h>
#include <math.h>

#define N_NODES 8192
#define NEDGE   131072
#define BGR     32
#define NELEM   5
#define NCOMP   160
#define NPAIR   800          // 32 graphs * 5 * 5
#define HH      128
#define GG      50
#define LL      6
#define MT      256          // distance-table samples (halved: error margin is ~1000x)
#define NBCOL   (LL*HH)      // 768
#define EWMAX   20.0f

static __device__ float g_R[NPAIR*MT];        // pair x bin accumulation of C * hat-basis
static __device__ float g_csum[NPAIR];        // sum of C per pair
static __device__ int   g_counts[NCOMP];      // nodes per component
static __device__ float g_tableW[MT*NBCOL];   // ssp(edge_attr@w1+b1)@w2 sampled on grid
static __device__ float g_S[NPAIR*NBCOL];     // R @ tableW
static __device__ float g_xout[LL*NCOMP*HH];  // per-layer additive update to types

__device__ __forceinline__ float sspf(float x) {
    return fmaxf(x, 0.0f) + log1pf(expf(-fabsf(x))) - 0.69314718055994531f;
}

// --------------------------------------------------------------------------
__global__ void k_zero() {
    int i = blockIdx.x * blockDim.x + threadIdx.x;
    int stride = gridDim.x * blockDim.x;
    for (int j = i; j < NPAIR*MT;    j += stride) g_R[j]    = 0.0f;
    for (int j = i; j < NPAIR*NBCOL; j += stride) g_S[j]    = 0.0f;
    for (int j = i; j < NPAIR;       j += stride) g_csum[j] = 0.0f;
}

// --------------------------------------------------------------------------
// Single block: smem histogram of nodes per component (self-contained).
__global__ void k_counts(const int* __restrict__ comp_id) {
    __shared__ int cnt[NCOMP];
    int tid = threadIdx.x;
    if (tid < NCOMP) cnt[tid] = 0;
    __syncthreads();
    for (int n = tid; n < N_NODES; n += blockDim.x)
        atomicAdd(&cnt[comp_id[n]], 1);
    __syncthreads();
    if (tid < NCOMP) g_counts[tid] = cnt[tid];
}

// --------------------------------------------------------------------------
// Per-edge: distance, cutoff weight C, pair id, 2-point hat-basis scatter into R.
__global__ void k_edges(const float* __restrict__ pos,
                        const int*   __restrict__ comp_id,
                        const int*   __restrict__ ei) {
    const float INV_DELTA = (float)(MT - 1) / EWMAX;
    int e = blockIdx.x * blockDim.x + threadIdx.x;
    if (e >= NEDGE) return;
    int s = ei[e];
    int d = ei[NEDGE + e];
    int cs = comp_id[s];
    int cd = comp_id[d];
    float dx = pos[3*s+0] - pos[3*d+0];
    float dy = pos[3*s+1] - pos[3*d+1];
    float dz = pos[3*s+2] - pos[3*d+2];
    float ew = sqrtf(dx*dx + dy*dy + dz*dz);
    float C  = 10.0f / (1e-10f + ew*ew) - 1.0f;
    int p = (cd / NELEM) * 25 + (cs % NELEM) * NELEM + (cd % NELEM);
    float tf = fminf(ew * INV_DELTA, (float)(MT - 1));
    int   i0 = min((int)tf, MT - 2);
    float fr = tf - (float)i0;
    atomicAdd(&g_R[p*MT + i0],     C * (1.0f - fr));
    atomicAdd(&g_R[p*MT + i0 + 1], C * fr);
    atomicAdd(&g_csum[p], C);
}

// --------------------------------------------------------------------------
// Fused: phi[m][f] = ssp(gauss(t_m)@w1[l] + b1[l]); tableW[m][l*H+f] = phi@w2[l].
// Grid (MT/4, LL), block 128. 384 blocks -> latency fully hidden.
__global__ void __launch_bounds__(128) k_phitw(
        const float* __restrict__ w1, const float* __restrict__ b1,
        const float* __restrict__ w2) {
    const float DELTA = EWMAX / (float)(MT - 1);
    const float OFFD  = 10.0f / 49.0f;
    const float COEFF = -0.5f / (OFFD * OFFD);
    __shared__ float a[4][GG];
    __shared__ float phi_s[4][HH];
    int m0 = blockIdx.x * 4;
    int l  = blockIdx.y;
    int f  = threadIdx.x;

    for (int idx = f; idx < 4*GG; idx += 128) {
        int mm = idx / GG, g = idx % GG;
        float t  = (float)(m0 + mm) * DELTA;
        float dt = t - (float)g * OFFD;
        a[mm][g] = expf(COEFF * dt * dt);
    }
    __syncthreads();

    float acc[4];
    float bb = b1[l*HH + f];
    #pragma unroll
    for (int mm = 0; mm < 4; mm++) acc[mm] = bb;
    #pragma unroll 5
    for (int g = 0; g < GG; g++) {
        float w = w1[(l*GG + g)*HH + f];
        #pragma unroll
        for (int mm = 0; mm < 4; mm++) acc[mm] += a[mm][g] * w;
    }
    #pragma unroll
    for (int mm = 0; mm < 4; mm++) phi_s[mm][f] = sspf(acc[mm]);
    __syncthreads();

    float t4[4] = {0.f, 0.f, 0.f, 0.f};
    #pragma unroll 8
    for (int k = 0; k < HH; k++) {
        float w = w2[(l*HH + k)*HH + f];
        #pragma unroll
        for (int mm = 0; mm < 4; mm++) t4[mm] += phi_s[mm][k] * w;
    }
    #pragma unroll
    for (int mm = 0; mm < 4; mm++)
        g_tableW[(m0 + mm)*NBCOL + l*HH + f] = t4[mm];
}

// --------------------------------------------------------------------------
// S[800,768] = R[800,256] @ tableW[256,768], split-K=4 with atomic accumulate.
#define BM 64
#define BN 128
#define BK 32
#define KSPLIT 4
__global__ void __launch_bounds__(256) k_gemm() {
    __shared__ float Rs[BM][BK + 1];
    __shared__ float Ts[BK][BN];
    int tid  = threadIdx.x;            // 256
    int row0 = blockIdx.x * BM;
    int col0 = blockIdx.y * BN;
    int kb   = blockIdx.z * (MT / KSPLIT);
    int ty = tid >> 5, tx = tid & 31;
    int r0 = ty * 8,   c0 = tx * 4;
    float acc[8][4];
    #pragma unroll
    for (int i = 0; i < 8; i++)
        #pragma unroll
        for (int j = 0; j < 4; j++) acc[i][j] = 0.0f;

    for (int kk = 0; kk < MT/KSPLIT; kk += BK) {
        int lr = tid >> 2;
        int lk = (tid & 3) * 8;
        int grow = row0 + lr;
        #pragma unroll
        for (int i = 0; i < 8; i++)
            Rs[lr][lk + i] = (grow < NPAIR) ? g_R[grow*MT + kb + kk + lk + i] : 0.0f;
        int tc  = (tid & 31) * 4;
        int tr0 = tid >> 5;
        #pragma unroll
        for (int j = 0; j < 4; j++) {
            int r = tr0 + j * 8;
            float4 v = *reinterpret_cast<const float4*>(
                &g_tableW[(kb + kk + r)*NBCOL + col0 + tc]);
            *reinterpret_cast<float4*>(&Ts[r][tc]) = v;
        }
        __syncthreads();
        #pragma unroll
        for (int k = 0; k < BK; k++) {
            float4 b = *reinterpret_cast<const float4*>(&Ts[k][c0]);
            #pragma unroll
            for (int i = 0; i < 8; i++) {
                float a = Rs[r0 + i][k];
                acc[i][0] += a * b.x;
                acc[i][1] += a * b.y;
                acc[i][2] += a * b.z;
                acc[i][3] += a * b.w;
            }
        }
        __syncthreads();
    }
    #pragma unroll
    for (int i = 0; i < 8; i++) {
        int gr = row0 + r0 + i;
        if (gr < NPAIR) {
            #pragma unroll
            for (int j = 0; j < 4; j++)
                atomicAdd(&g_S[gr*NBCOL + col0 + c0 + j], acc[i][j]);
        }
    }
}

// --------------------------------------------------------------------------
// Per (graph, layer): comp -> cf_lin2 -> ssp -> int_lin. 5-way ILP on targets.
__global__ void __launch_bounds__(128) k_comp(
                       const int*   __restrict__ comps_z,
                       const float* __restrict__ emb,
                       const float* __restrict__ cf1,
                       const float* __restrict__ b2,
                       const float* __restrict__ cf2w,
                       const float* __restrict__ cf2b,
                       const float* __restrict__ ilw,
                       const float* __restrict__ ilb) {
    __shared__ float semb[NELEM][HH];
    __shared__ float xh  [NELEM][HH];
    __shared__ float buf [NELEM][HH];
    int g = blockIdx.x, l = blockIdx.y;
    int f = threadIdx.x;

    #pragma unroll
    for (int s = 0; s < NELEM; s++)
        semb[s][f] = emb[comps_z[g*NELEM + s]*HH + f];
    __syncthreads();

    // xh[s] = emb_s @ cf_lin1  (5 concurrent accumulators, 1 load / 5 FMA)
    {
        float acc[NELEM] = {0.f, 0.f, 0.f, 0.f, 0.f};
        #pragma unroll 8
        for (int h = 0; h < HH; h++) {
            float w = cf1[(l*HH + h)*HH + f];
            #pragma unroll
            for (int s = 0; s < NELEM; s++) acc[s] += semb[s][h] * w;
        }
        #pragma unroll
        for (int s = 0; s < NELEM; s++) xh[s][f] = acc[s];
    }
    __syncthreads();

    // comp[t] = (1/count) * sum_s xh[s] * (S[p(s,t)] + b2*csum[p])
    float bb2 = b2[l*HH + f];
    #pragma unroll
    for (int t = 0; t < NELEM; t++) {
        float acc = 0.0f;
        #pragma unroll
        for (int s = 0; s < NELEM; s++) {
            int p = g*25 + s*NELEM + t;
            float Sv = g_S[p*NBCOL + l*HH + f] + bb2 * g_csum[p];
            acc += xh[s][f] * Sv;
        }
        buf[t][f] = acc / (float)g_counts[g*NELEM + t];
    }
    __syncthreads();

    // x1[t] = ssp(comp[t] @ cf_lin2 + cf2b)
    {
        float acc[NELEM];
        float cb = cf2b[l*HH + f];
        #pragma unroll
        for (int t = 0; t < NELEM; t++) acc[t] = cb;
        #pragma unroll 8
        for (int h = 0; h < HH; h++) {
            float w = cf2w[(l*HH + h)*HH + f];
            #pragma unroll
            for (int t = 0; t < NELEM; t++) acc[t] += buf[t][h] * w;
        }
        __syncthreads();
        #pragma unroll
        for (int t = 0; t < NELEM; t++) xh[t][f] = sspf(acc[t]);
    }
    __syncthreads();

    // xout[t] = x1[t] @ int_lin + ilb
    {
        float acc[NELEM];
        float ib = ilb[l*HH + f];
        #pragma unroll
        for (int t = 0; t < NELEM; t++) acc[t] = ib;
        #pragma unroll 8
        for (int h = 0; h < HH; h++) {
            float w = ilw[(l*HH + h)*HH + f];
            #pragma unroll
            for (int t = 0; t < NELEM; t++) acc[t] += xh[t][h] * w;
        }
        #pragma unroll
        for (int t = 0; t < NELEM; t++)
            g_xout[(l*NCOMP + g*NELEM + t)*HH + f] = acc[t];
    }
}

// --------------------------------------------------------------------------
// Readout per graph: types = emb + sum_l x_l ; out[g] = sum_c (ssp(types@w1+b1)@w2 + b2)
__global__ void __launch_bounds__(128) k_readout(
                          const int*   __restrict__ comps_z,
                          const float* __restrict__ emb,
                          const float* __restrict__ ow1,
                          const float* __restrict__ ob1,
                          const float* __restrict__ ow2,
                          const float* __restrict__ ob2,
                          float* __restrict__ out) {
    __shared__ float types[NELEM][HH];
    __shared__ float wsum[2];
    int g = blockIdx.x;
    int tid = threadIdx.x;  // 128

    #pragma unroll
    for (int s = 0; s < NELEM; s++) {
        int c = g*NELEM + s;
        float v = emb[comps_z[c]*HH + tid];
        #pragma unroll
        for (int l = 0; l < LL; l++) v += g_xout[(l*NCOMP + c)*HH + tid];
        types[s][tid] = v;
    }
    __syncthreads();

    float pc = 0.0f;
    if (tid < 64) {
        #pragma unroll
        for (int s = 0; s < NELEM; s++) {
            float u = ob1[tid];
            #pragma unroll 8
            for (int h = 0; h < HH; h++) u += types[s][h] * ow1[h*64 + tid];
            pc += sspf(u) * ow2[tid];
        }
    }
    #pragma unroll
    for (int off = 16; off > 0; off >>= 1)
        pc += __shfl_down_sync(0xffffffff, pc, off);
    if ((tid & 31) == 0 && tid < 64) wsum[tid >> 5] = pc;
    __syncthreads();
    if (tid == 0) out[g] = wsum[0] + wsum[1] + 5.0f * ob2[0];
}

// --------------------------------------------------------------------------
extern "C" void kernel_launch(void* const* d_in, const int* in_sizes, int n_in,
                              void* d_out, int out_size) {
    const float* pos      = (const float*)d_in[0];
    const float* emb      = (const float*)d_in[1];
    const float* mlp_w1   = (const float*)d_in[2];
    const float* mlp_b1   = (const float*)d_in[3];
    const float* mlp_w2   = (const float*)d_in[4];
    const float* mlp_b2   = (const float*)d_in[5];
    const float* cf1w     = (const float*)d_in[6];
    const float* cf2w     = (const float*)d_in[7];
    const float* cf2b     = (const float*)d_in[8];
    const float* ilw      = (const float*)d_in[9];
    const float* ilb      = (const float*)d_in[10];
    const float* ow1      = (const float*)d_in[11];
    const float* ob1      = (const float*)d_in[12];
    const float* ow2      = (const float*)d_in[13];
    const float* ob2      = (const float*)d_in[14];
    // d_in[15] = z (unused: z[n] == comps_z[comp_id[n]] by construction)
    const int*   comp_id  = (const int*)d_in[16];
    const int*   ei       = (const int*)d_in[17];
    const int*   comps_z  = (const int*)d_in[18];
    float*       out      = (float*)d_out;

    k_zero   <<<256, 256>>>();
    k_counts <<<1, 1024>>>(comp_id);
    k_edges  <<<(NEDGE + 255)/256, 256>>>(pos, comp_id, ei);
    k_phitw  <<<dim3(MT/4, LL), 128>>>(mlp_w1, mlp_b1, mlp_w2);
    k_gemm   <<<dim3((NPAIR + BM - 1)/BM, NBCOL/BN, KSPLIT), 256>>>();
    k_comp   <<<dim3(BGR, LL), 128>>>(comps_z, emb, cf1w, mlp_b2, cf2w, cf2b, ilw, ilb);
    k_readout<<<BGR, 128>>>(comps_z, emb, ow1, ob1, ow2, ob2, out);
}